// round 3
// baseline (speedup 1.0000x reference)
#include <cuda_runtime.h>
#include <cstdint>
#include <cstddef>

#define N_TOK   131072
#define DIM     64
#define KCODES  1024
#define CHUNK   64          // codes per smem chunk (duplicated pairs: 64*64*8 = 32KB)
#define QBLOCKS 512         // quantize kernel blocks (256 tokens each)

// Output layout (float32, flattened tuple order):
//   [0]                      loss
//   [1 .. 1+N*D)             quantized_st
//   [1+N*D]                  perplexity
//   [2+N*D .. 2+N*D+N)       encoding_indices (as float)
#define OUT_Q    ((size_t)1)
#define OUT_PERP ((size_t)1 + (size_t)N_TOK * DIM)
#define OUT_IDX  ((size_t)2 + (size_t)N_TOK * DIM)

typedef unsigned long long u64;

// ---------------- device scratch (no allocations allowed) ----------------
__device__ float  g_e2[KCODES];
__device__ int    g_idx[N_TOK];
__device__ int    g_counts[KCODES];
__device__ double g_block_sse[QBLOCKS];

// ---------------- packed f32x2 helpers (FFMA2 path, sm_103a) -------------
__device__ __forceinline__ void ffma2(u64& d, u64 a, u64 b) {
    asm("fma.rn.f32x2 %0, %1, %2, %0;" : "+l"(d) : "l"(a), "l"(b));
}
__device__ __forceinline__ u64 fadd2(u64 a, u64 b) {
    u64 d; asm("add.rn.f32x2 %0, %1, %2;" : "=l"(d) : "l"(a), "l"(b)); return d;
}
__device__ __forceinline__ u64 pack2(float x, float y) {
    u64 v; asm("mov.b64 %0, {%1, %2};" : "=l"(v) : "f"(x), "f"(y)); return v;
}
__device__ __forceinline__ float2 unpack2(u64 v) {
    float2 f; asm("mov.b64 {%0, %1}, %2;" : "=f"(f.x), "=f"(f.y) : "l"(v)); return f;
}

// ---------------- kernel 0: prep (e2 per code, zero counts) --------------
__global__ void vq_prep_kernel(const float* __restrict__ cb) {
    int k = blockIdx.x * blockDim.x + threadIdx.x;
    if (k < KCODES) {
        const float* row = cb + (size_t)k * DIM;
        float s0 = 0.f, s1 = 0.f, s2 = 0.f, s3 = 0.f;
        #pragma unroll
        for (int i = 0; i < DIM; i += 4) {
            s0 = fmaf(row[i+0], row[i+0], s0);
            s1 = fmaf(row[i+1], row[i+1], s1);
            s2 = fmaf(row[i+2], row[i+2], s2);
            s3 = fmaf(row[i+3], row[i+3], s3);
        }
        g_e2[k] = (s0 + s1) + (s2 + s3);
        g_counts[k] = 0;
    }
}

// ---------------- kernel 1: argmin (the hot GEMM-like kernel) ------------
// Grid: 256 CTAs x 256 threads. Each thread owns 2 consecutive tokens,
// packed into f32x2 lanes. Codebook streamed via smem in duplicated pairs.
__global__ void __launch_bounds__(256, 1)
vq_argmin_kernel(const float* __restrict__ x, const float* __restrict__ cb,
                 float* __restrict__ out_idx_f) {
    __shared__ __align__(16) u64  s_e[CHUNK * DIM];   // duplicated (e,e) pairs, 32KB
    __shared__ float s_e2[CHUNK];

    const int tid = blockIdx.x * 256 + threadIdx.x;   // pair index in [0, 65536)
    const int t0 = 2 * tid;
    const int t1 = t0 + 1;

    // Load 2 token rows, pack lane-wise: px[i] = (x_t0[i], x_t1[i])
    u64 px[DIM];
    {
        const float4* r0 = reinterpret_cast<const float4*>(x + (size_t)t0 * DIM);
        const float4* r1 = reinterpret_cast<const float4*>(x + (size_t)t1 * DIM);
        #pragma unroll
        for (int i = 0; i < DIM / 4; ++i) {
            float4 a = r0[i], b = r1[i];
            px[4*i+0] = pack2(a.x, b.x);
            px[4*i+1] = pack2(a.y, b.y);
            px[4*i+2] = pack2(a.z, b.z);
            px[4*i+3] = pack2(a.w, b.w);
        }
    }

    // |x|^2 per token (packed)
    float2 x2;
    {
        u64 q0 = 0ull, q1 = 0ull, q2 = 0ull, q3 = 0ull;
        #pragma unroll
        for (int i = 0; i < DIM / 4; ++i) {
            ffma2(q0, px[4*i+0], px[4*i+0]);
            ffma2(q1, px[4*i+1], px[4*i+1]);
            ffma2(q2, px[4*i+2], px[4*i+2]);
            ffma2(q3, px[4*i+3], px[4*i+3]);
        }
        x2 = unpack2(fadd2(fadd2(q0, q1), fadd2(q2, q3)));
    }

    float best0 = 3.4e38f, best1 = 3.4e38f;
    int   bi0 = 0, bi1 = 0;

    const float4* cb4 = reinterpret_cast<const float4*>(cb);

    #pragma unroll 1
    for (int c0 = 0; c0 < KCODES; c0 += CHUNK) {
        __syncthreads();
        // Cooperative load: CHUNK codes x 16 float4, duplicated into (e,e) pairs
        for (int j = threadIdx.x; j < CHUNK * (DIM / 4); j += 256) {
            int code = j >> 4, q = j & 15;
            float4 v = cb4[(size_t)(c0 + code) * (DIM / 4) + q];
            u64* dst = s_e + code * DIM + q * 4;
            dst[0] = pack2(v.x, v.x);
            dst[1] = pack2(v.y, v.y);
            dst[2] = pack2(v.z, v.z);
            dst[3] = pack2(v.w, v.w);
        }
        if (threadIdx.x < CHUNK) s_e2[threadIdx.x] = g_e2[c0 + threadIdx.x];
        __syncthreads();

        #pragma unroll 1
        for (int k = 0; k < CHUNK; ++k) {
            const ulonglong2* e = reinterpret_cast<const ulonglong2*>(s_e + k * DIM);
            u64 a0 = 0ull, a1 = 0ull, a2 = 0ull, a3 = 0ull;
            #pragma unroll
            for (int i = 0; i < DIM / 4; ++i) {
                ulonglong2 e0 = e[2*i];
                ulonglong2 e1 = e[2*i+1];
                ffma2(a0, px[4*i+0], e0.x);
                ffma2(a1, px[4*i+1], e0.y);
                ffma2(a2, px[4*i+2], e1.x);
                ffma2(a3, px[4*i+3], e1.y);
            }
            float2 dot = unpack2(fadd2(fadd2(a0, a1), fadd2(a2, a3)));
            float e2 = s_e2[k];
            // d = fl(x2 - 2*dot) + e2  (matches reference rounding structure)
            float d0 = fmaf(dot.x, -2.0f, x2.x) + e2;
            float d1 = fmaf(dot.y, -2.0f, x2.y) + e2;
            int kk = c0 + k;
            if (d0 < best0) { best0 = d0; bi0 = kk; }
            if (d1 < best1) { best1 = d1; bi1 = kk; }
        }
    }

    g_idx[t0] = bi0;
    g_idx[t1] = bi1;
    out_idx_f[t0] = (float)bi0;
    out_idx_f[t1] = (float)bi1;
}

// ---------------- kernel 2: quantize + MSE partials + histogram ----------
// Grid: 512 CTAs x 256 threads; each CTA handles 256 tokens.
// Thread = (token sub-slot, dim): tid = sub*64 + dim -> coalesced I/O.
__global__ void __launch_bounds__(256)
vq_quantize_kernel(const float* __restrict__ x, const float* __restrict__ cb,
                   float* __restrict__ dout) {
    __shared__ int   sbins[KCODES];
    __shared__ float swarp[8];

    for (int i = threadIdx.x; i < KCODES; i += 256) sbins[i] = 0;
    __syncthreads();

    const int dim  = threadIdx.x & 63;
    const int sub  = threadIdx.x >> 6;     // 0..3
    const int base = blockIdx.x * 256;

    float lsum = 0.f;
    #pragma unroll 4
    for (int it = 0; it < 64; ++it) {
        int t   = base + it * 4 + sub;
        int idx = g_idx[t];
        float q  = cb[(size_t)idx * DIM + dim];
        float xv = x[(size_t)t * DIM + dim];
        float df = q - xv;                              // quantized - inputs
        dout[OUT_Q + (size_t)t * DIM + dim] = xv + df;  // straight-through value
        lsum = fmaf(df, df, lsum);
        if (dim == 0) atomicAdd(&sbins[idx], 1);
    }

    // block-reduce lsum (deterministic tree)
    #pragma unroll
    for (int o = 16; o > 0; o >>= 1) lsum += __shfl_down_sync(0xffffffffu, lsum, o);
    if ((threadIdx.x & 31) == 0) swarp[threadIdx.x >> 5] = lsum;
    __syncthreads();
    if (threadIdx.x == 0) {
        float s = 0.f;
        #pragma unroll
        for (int w = 0; w < 8; ++w) s += swarp[w];
        g_block_sse[blockIdx.x] = (double)s;
    }

    // merge histogram (integer atomics: exact + deterministic)
    for (int i = threadIdx.x; i < KCODES; i += 256) {
        int c = sbins[i];
        if (c) atomicAdd(&g_counts[i], c);
    }
}

// ---------------- kernel 3: finalize loss + perplexity -------------------
__global__ void vq_finalize_kernel(float* __restrict__ dout) {
    __shared__ double sd[256];
    const int tid = threadIdx.x;

    // deterministic sum of per-block SSE
    double s = 0.0;
    for (int i = tid; i < QBLOCKS; i += 256) s += g_block_sse[i];
    sd[tid] = s;
    __syncthreads();
    #pragma unroll
    for (int o = 128; o > 0; o >>= 1) {
        if (tid < o) sd[tid] += sd[tid + o];
        __syncthreads();
    }
    double sse = sd[0];
    __syncthreads();

    // entropy: H = sum p*log(p + 1e-10), p = counts / N
    double h = 0.0;
    for (int i = tid; i < KCODES; i += 256) {
        float p = (float)g_counts[i] * (1.0f / (float)N_TOK);
        h += (double)(p * logf(p + 1e-10f));
    }
    sd[tid] = h;
    __syncthreads();
    #pragma unroll
    for (int o = 128; o > 0; o >>= 1) {
        if (tid < o) sd[tid] += sd[tid + o];
        __syncthreads();
    }

    if (tid == 0) {
        float mse = (float)(sse / ((double)N_TOK * (double)DIM));
        dout[0]        = mse + 0.25f * mse;          // (1 + beta) * mse
        dout[OUT_PERP] = expf((float)(-sd[0]));      // exp(-sum p log p)
    }
}

// ---------------- launch ---------------------------------------------------
extern "C" void kernel_launch(void* const* d_in, const int* in_sizes, int n_in,
                              void* d_out, int out_size) {
    const float* x  = (const float*)d_in[0];
    const float* cb = (const float*)d_in[1];
    // defensive: metadata order is (inputs, codebook); swap if sizes disagree
    if (n_in >= 2 && in_sizes[0] == KCODES * DIM && in_sizes[1] == N_TOK * DIM) {
        const float* t = x; x = cb; cb = t;
    }
    float* out = (float*)d_out;

    vq_prep_kernel<<<(KCODES + 255) / 256, 256>>>(cb);
    vq_argmin_kernel<<<(N_TOK / 2) / 256, 256>>>(x, cb, out + OUT_IDX);
    vq_quantize_kernel<<<QBLOCKS, 256>>>(x, cb, out);
    vq_finalize_kernel<<<1, 256>>>(out);
}

// round 5
// speedup vs baseline: 1.4193x; 1.4193x over previous
#include <cuda_runtime.h>
#include <cstdint>
#include <cstddef>

#define N_TOK   131072
#define DIM     64
#define KCODES  1024
#define CHUNK   64          // codes per smem chunk (raw floats: 64*64*4 = 16KB)
#define QBLOCKS 512         // quantize kernel blocks (256 tokens each)

// Output layout (float32, flattened tuple order):
//   [0]                      loss
//   [1 .. 1+N*D)             quantized_st
//   [1+N*D]                  perplexity
//   [2+N*D .. 2+N*D+N)       encoding_indices (as float)
#define OUT_Q    ((size_t)1)
#define OUT_PERP ((size_t)1 + (size_t)N_TOK * DIM)
#define OUT_IDX  ((size_t)2 + (size_t)N_TOK * DIM)

typedef unsigned long long u64;

// ---------------- device scratch (no allocations allowed) ----------------
__device__ float  g_e2[KCODES];
__device__ int    g_idx[N_TOK];
__device__ int    g_counts[KCODES];
__device__ double g_block_sse[QBLOCKS];

// ---------------- packed f32x2 helpers (FFMA2 path, sm_103a) -------------
__device__ __forceinline__ void ffma2(u64& d, u64 a, u64 b) {
    asm("fma.rn.f32x2 %0, %1, %2, %0;" : "+l"(d) : "l"(a), "l"(b));
}
__device__ __forceinline__ float2 unpack2(u64 v) {
    float2 f; asm("mov.b64 {%0, %1}, %2;" : "=f"(f.x), "=f"(f.y) : "l"(v)); return f;
}

// ---------------- kernel 0: prep (e2 per code, zero counts) --------------
__global__ void vq_prep_kernel(const float* __restrict__ cb) {
    int k = blockIdx.x * blockDim.x + threadIdx.x;
    if (k < KCODES) {
        const float* row = cb + (size_t)k * DIM;
        float s0 = 0.f, s1 = 0.f, s2 = 0.f, s3 = 0.f;
        #pragma unroll
        for (int i = 0; i < DIM; i += 4) {
            s0 = fmaf(row[i+0], row[i+0], s0);
            s1 = fmaf(row[i+1], row[i+1], s1);
            s2 = fmaf(row[i+2], row[i+2], s2);
            s3 = fmaf(row[i+3], row[i+3], s3);
        }
        g_e2[k] = (s0 + s1) + (s2 + s3);
        g_counts[k] = 0;
    }
}

// ---------------- kernel 1: argmin (the hot GEMM-like kernel) ------------
// 128 threads/CTA, occ 3 (3 warps/SMSP). Each thread owns 2 consecutive
// tokens, dims packed pairwise as f32x2: px_t[j] = (x[2j], x[2j+1]).
// Codebook chunk lives raw in smem; each LDS.128 feeds 4 FFMA2.
__global__ void __launch_bounds__(128, 3)
vq_argmin_kernel(const float* __restrict__ x, const float* __restrict__ cb,
                 float* __restrict__ out_idx_f) {
    __shared__ __align__(16) float s_e[CHUNK * DIM];   // raw chunk, 16KB
    __shared__ float s_e2[CHUNK];

    const int tid = blockIdx.x * 128 + threadIdx.x;    // pair index in [0, 65536)
    const int t0 = 2 * tid;
    const int t1 = t0 + 1;

    // Load 2 token rows; consecutive-dim pairs are already f32x2 operands.
    u64 px0[DIM / 2], px1[DIM / 2];
    {
        const ulonglong2* r0 = reinterpret_cast<const ulonglong2*>(x + (size_t)t0 * DIM);
        const ulonglong2* r1 = reinterpret_cast<const ulonglong2*>(x + (size_t)t1 * DIM);
        #pragma unroll
        for (int i = 0; i < DIM / 4; ++i) {
            ulonglong2 a = r0[i]; px0[2*i] = a.x; px0[2*i+1] = a.y;
            ulonglong2 b = r1[i]; px1[2*i] = b.x; px1[2*i+1] = b.y;
        }
    }

    // |x|^2 per token
    float x20, x21;
    {
        u64 qa = 0ull, qb = 0ull;
        #pragma unroll
        for (int j = 0; j < DIM / 2; ++j) {
            ffma2(qa, px0[j], px0[j]);
            ffma2(qb, px1[j], px1[j]);
        }
        float2 fa = unpack2(qa), fb = unpack2(qb);
        x20 = fa.x + fa.y;
        x21 = fb.x + fb.y;
    }

    float best0 = 3.4e38f, best1 = 3.4e38f;
    int   bi0 = 0, bi1 = 0;

    const float4* cb4 = reinterpret_cast<const float4*>(cb);

    for (int c0 = 0; c0 < KCODES; c0 += CHUNK) {
        __syncthreads();
        // Cooperative raw copy: CHUNK*DIM floats = 1024 float4 over 128 threads
        {
            const float4* src = cb4 + (size_t)c0 * (DIM / 4);
            float4* dst = reinterpret_cast<float4*>(s_e);
            #pragma unroll
            for (int j = 0; j < CHUNK * (DIM / 4) / 128; ++j)
                dst[j * 128 + threadIdx.x] = src[j * 128 + threadIdx.x];
        }
        if (threadIdx.x < CHUNK) s_e2[threadIdx.x] = g_e2[c0 + threadIdx.x];
        __syncthreads();

        #pragma unroll 2
        for (int k = 0; k < CHUNK; ++k) {
            const ulonglong2* e = reinterpret_cast<const ulonglong2*>(s_e + k * DIM);
            u64 a = 0ull, b = 0ull;   // packed (even,odd) chains per token
            #pragma unroll
            for (int i = 0; i < DIM / 4; ++i) {
                ulonglong2 ev = e[i];                 // one LDS.128 -> 4 FFMA2
                ffma2(a, px0[2*i],   ev.x);
                ffma2(a, px0[2*i+1], ev.y);
                ffma2(b, px1[2*i],   ev.x);
                ffma2(b, px1[2*i+1], ev.y);
            }
            float2 fa = unpack2(a), fb = unpack2(b);
            float dot0 = fa.x + fa.y;
            float dot1 = fb.x + fb.y;
            float e2 = s_e2[k];
            // d = fl(x2 - 2*dot) + e2  (exactly the reference rounding structure)
            float d0 = fmaf(dot0, -2.0f, x20) + e2;
            float d1 = fmaf(dot1, -2.0f, x21) + e2;
            int kk = c0 + k;
            if (d0 < best0) { best0 = d0; bi0 = kk; }
            if (d1 < best1) { best1 = d1; bi1 = kk; }
        }
    }

    g_idx[t0] = bi0;
    g_idx[t1] = bi1;
    out_idx_f[t0] = (float)bi0;
    out_idx_f[t1] = (float)bi1;
}

// ---------------- kernel 2: quantize + MSE partials + histogram ----------
// 512 CTAs x 256 threads; each CTA handles 256 tokens.
// Thread = (token sub-slot, dim): tid = sub*64 + dim -> coalesced I/O.
// NOTE: output region starts at dout+1 (4B offset) -> stores MUST be scalar.
__global__ void __launch_bounds__(256)
vq_quantize_kernel(const float* __restrict__ x, const float* __restrict__ cb,
                   float* __restrict__ dout) {
    __shared__ int   sbins[KCODES];
    __shared__ float swarp[8];

    for (int i = threadIdx.x; i < KCODES; i += 256) sbins[i] = 0;
    __syncthreads();

    const int dim  = threadIdx.x & 63;
    const int sub  = threadIdx.x >> 6;     // 0..3
    const int base = blockIdx.x * 256;

    float lsum = 0.f;
    #pragma unroll 4
    for (int it = 0; it < 64; ++it) {
        int t   = base + it * 4 + sub;
        int idx = g_idx[t];
        float q  = cb[(size_t)idx * DIM + dim];
        float xv = x[(size_t)t * DIM + dim];
        float df = q - xv;                              // quantized - inputs
        dout[OUT_Q + (size_t)t * DIM + dim] = xv + df;  // straight-through value
        lsum = fmaf(df, df, lsum);
        if (dim == 0) atomicAdd(&sbins[idx], 1);
    }

    // block-reduce lsum (deterministic tree)
    #pragma unroll
    for (int o = 16; o > 0; o >>= 1) lsum += __shfl_down_sync(0xffffffffu, lsum, o);
    if ((threadIdx.x & 31) == 0) swarp[threadIdx.x >> 5] = lsum;
    __syncthreads();
    if (threadIdx.x == 0) {
        float s = 0.f;
        #pragma unroll
        for (int w = 0; w < 8; ++w) s += swarp[w];
        g_block_sse[blockIdx.x] = (double)s;
    }

    // merge histogram (integer atomics: exact + deterministic)
    for (int i = threadIdx.x; i < KCODES; i += 256) {
        int c = sbins[i];
        if (c) atomicAdd(&g_counts[i], c);
    }
}

// ---------------- kernel 3: finalize loss + perplexity -------------------
__global__ void vq_finalize_kernel(float* __restrict__ dout) {
    __shared__ double sd[256];
    const int tid = threadIdx.x;

    // deterministic sum of per-block SSE
    double s = 0.0;
    for (int i = tid; i < QBLOCKS; i += 256) s += g_block_sse[i];
    sd[tid] = s;
    __syncthreads();
    #pragma unroll
    for (int o = 128; o > 0; o >>= 1) {
        if (tid < o) sd[tid] += sd[tid + o];
        __syncthreads();
    }
    double sse = sd[0];
    __syncthreads();

    // entropy: H = sum p*log(p + 1e-10), p = counts / N
    double h = 0.0;
    for (int i = tid; i < KCODES; i += 256) {
        float p = (float)g_counts[i] * (1.0f / (float)N_TOK);
        h += (double)(p * logf(p + 1e-10f));
    }
    sd[tid] = h;
    __syncthreads();
    #pragma unroll
    for (int o = 128; o > 0; o >>= 1) {
        if (tid < o) sd[tid] += sd[tid + o];
        __syncthreads();
    }

    if (tid == 0) {
        float mse = (float)(sse / ((double)N_TOK * (double)DIM));
        dout[0]        = mse + 0.25f * mse;          // (1 + beta) * mse
        dout[OUT_PERP] = expf((float)(-sd[0]));      // exp(-sum p log p)
    }
}

// ---------------- launch ---------------------------------------------------
extern "C" void kernel_launch(void* const* d_in, const int* in_sizes, int n_in,
                              void* d_out, int out_size) {
    const float* x  = (const float*)d_in[0];
    const float* cb = (const float*)d_in[1];
    // defensive: metadata order is (inputs, codebook); swap if sizes disagree
    if (n_in >= 2 && in_sizes[0] == KCODES * DIM && in_sizes[1] == N_TOK * DIM) {
        const float* t = x; x = cb; cb = t;
    }
    float* out = (float*)d_out;

    vq_prep_kernel<<<(KCODES + 255) / 256, 256>>>(cb);
    vq_argmin_kernel<<<(N_TOK / 2) / 128, 128>>>(x, cb, out + OUT_IDX);
    vq_quantize_kernel<<<QBLOCKS, 256>>>(x, cb, out);
    vq_finalize_kernel<<<1, 256>>>(out);
}